// round 1
// baseline (speedup 1.0000x reference)
#include <cuda_runtime.h>

#define S_LEN 4096
#define D_MODEL 1024
#define N_HEADS 16
#define HEAD_DIM 64
#define HALF_DIM 32

// Scratch (device globals; no allocations allowed)
__device__ float g_qt[N_HEADS * HEAD_DIM * S_LEN]; // [h][d][s]  (RoPE'd Q)
__device__ float g_kt[N_HEADS * HEAD_DIM * S_LEN]; // [h][d][s]  (RoPE'd K)
__device__ float g_vt[N_HEADS * S_LEN * HEAD_DIM]; // [h][s][d]
__device__ float g_at[S_LEN * D_MODEL];            // attention out [s][h*64+d]

enum { MODE_Q = 0, MODE_K = 1, MODE_V = 2, MODE_O = 3 };

// C = X[M,K] @ W^T (W is [N,K] row-major) + bias, with mode-specific epilogue.
// M = S_LEN, N = K = D_MODEL. BM=BN=128, BK=16, 256 threads, 8x8 per thread.
template <int MODE>
__global__ void __launch_bounds__(256) gemm_k(
    const float* __restrict__ Xin, const float* __restrict__ W,
    const float* __restrict__ bias, const float* __restrict__ fcos,
    const float* __restrict__ fsin, float* __restrict__ oout)
{
    const float* X = (MODE == MODE_O) ? (const float*)g_at : Xin;
    float* dst = (MODE == MODE_Q) ? g_qt
               : (MODE == MODE_K) ? g_kt
               : (MODE == MODE_V) ? g_vt
               : oout;

    __shared__ float As[16][132]; // [k][m], padded stride 132 (16B-aligned rows)
    __shared__ float Bs[16][132]; // [k][n]

    const int K = D_MODEL;
    int bm = blockIdx.y * 128;
    int bn = blockIdx.x * 128;
    int tid = threadIdx.x;
    int tx = tid & 15;
    int ty = tid >> 4;
    int lr = tid >> 1;         // 0..127 : row within tile
    int lc = (tid & 1) << 3;   // 0 or 8 : k-column base

    const float* Ap = X + (size_t)(bm + lr) * K + lc;
    const float* Bp = W + (size_t)(bn + lr) * K + lc;

    float acc[8][8];
#pragma unroll
    for (int i = 0; i < 8; i++)
#pragma unroll
        for (int j = 0; j < 8; j++) acc[i][j] = 0.f;

    for (int k0 = 0; k0 < K; k0 += 16) {
        float4 a0 = *(const float4*)(Ap + k0);
        float4 a1 = *(const float4*)(Ap + k0 + 4);
        float4 b0 = *(const float4*)(Bp + k0);
        float4 b1 = *(const float4*)(Bp + k0 + 4);
        __syncthreads();
        As[lc + 0][lr] = a0.x; As[lc + 1][lr] = a0.y;
        As[lc + 2][lr] = a0.z; As[lc + 3][lr] = a0.w;
        As[lc + 4][lr] = a1.x; As[lc + 5][lr] = a1.y;
        As[lc + 6][lr] = a1.z; As[lc + 7][lr] = a1.w;
        Bs[lc + 0][lr] = b0.x; Bs[lc + 1][lr] = b0.y;
        Bs[lc + 2][lr] = b0.z; Bs[lc + 3][lr] = b0.w;
        Bs[lc + 4][lr] = b1.x; Bs[lc + 5][lr] = b1.y;
        Bs[lc + 6][lr] = b1.z; Bs[lc + 7][lr] = b1.w;
        __syncthreads();
#pragma unroll
        for (int kk = 0; kk < 16; kk++) {
            float af[8], bf[8];
            *(float4*)(af + 0) = *(const float4*)&As[kk][ty * 8];
            *(float4*)(af + 4) = *(const float4*)&As[kk][ty * 8 + 4];
            *(float4*)(bf + 0) = *(const float4*)&Bs[kk][tx * 8];
            *(float4*)(bf + 4) = *(const float4*)&Bs[kk][tx * 8 + 4];
#pragma unroll
            for (int i = 0; i < 8; i++)
#pragma unroll
                for (int j = 0; j < 8; j++)
                    acc[i][j] = fmaf(af[i], bf[j], acc[i][j]);
        }
    }

    int rbase = bm + ty * 8;
    int cbase = bn + tx * 8;

    if (MODE == MODE_O) {
#pragma unroll
        for (int i = 0; i < 8; i++) {
            size_t ro = (size_t)(rbase + i) * D_MODEL + cbase;
#pragma unroll
            for (int j = 0; j < 8; j++)
                dst[ro + j] = acc[i][j] + bias[cbase + j];
        }
    } else if (MODE == MODE_V) {
        // write [h][s][d]
        int h = cbase >> 6;
        int d0 = cbase & 63;
#pragma unroll
        for (int i = 0; i < 8; i++) {
            size_t ro = (size_t)h * S_LEN * HEAD_DIM +
                        (size_t)(rbase + i) * HEAD_DIM + d0;
#pragma unroll
            for (int j = 0; j < 8; j++)
                dst[ro + j] = acc[i][j] + bias[cbase + j];
        }
    } else {
        // Q/K: RoPE in-register, write [h][d][s]
        int h = cbase >> 6;
        int d0 = cbase & 63;
        size_t hb = (size_t)h * HEAD_DIM * S_LEN;
#pragma unroll
        for (int i = 0; i < 8; i++) {
            int s = rbase + i;
#pragma unroll
            for (int jp = 0; jp < 4; jp++) {
                int d = d0 + jp * 2;
                float c  = fcos[s * HALF_DIM + (d >> 1)];
                float sn = fsin[s * HALF_DIM + (d >> 1)];
                float a0v = acc[i][jp * 2 + 0] + bias[cbase + jp * 2 + 0];
                float a1v = acc[i][jp * 2 + 1] + bias[cbase + jp * 2 + 1];
                dst[hb + (size_t)d * S_LEN + s]       = a0v * c - a1v * sn;
                dst[hb + (size_t)(d + 1) * S_LEN + s] = a0v * sn + a1v * c;
            }
        }
    }
}

// Flash attention, fp32. Grid: (S/64, H). 256 threads, 4x4 micro-tiles.
// Q/K read as [h][d][s] (no smem transpose needed); V as [h][s][d].
__global__ void __launch_bounds__(256) attn_k()
{
    __shared__ float Qs[64][64];   // [d][i]
    __shared__ float KVs[64][64];  // K phase: [d][j] ; V phase: [j][d]
    __shared__ float Ps[64 * 64];  // probs, transposed w/ rotation swizzle

    int qb = gridDim.x - 1 - blockIdx.x;  // longest blocks first
    int h = blockIdx.y;
    int tid = threadIdx.x;
    int tx = tid & 15;
    int ty = tid >> 4;
    int lr = tid >> 2;        // 0..63
    int lc = (tid & 3) << 4;  // 0,16,32,48

    const float* qg = g_qt + (size_t)h * HEAD_DIM * S_LEN;
    const float* kg = g_kt + (size_t)h * HEAD_DIM * S_LEN;
    const float* vg = g_vt + (size_t)h * S_LEN * HEAD_DIM;

    {
        const float* p = qg + (size_t)lr * S_LEN + qb * 64 + lc;
        *(float4*)&Qs[lr][lc + 0]  = *(const float4*)(p + 0);
        *(float4*)&Qs[lr][lc + 4]  = *(const float4*)(p + 4);
        *(float4*)&Qs[lr][lc + 8]  = *(const float4*)(p + 8);
        *(float4*)&Qs[lr][lc + 12] = *(const float4*)(p + 12);
    }

    float m[4], l[4], o[4][4];
#pragma unroll
    for (int i = 0; i < 4; i++) {
        m[i] = -1e30f;
        l[i] = 0.f;
#pragma unroll
        for (int j = 0; j < 4; j++) o[i][j] = 0.f;
    }

    for (int kb = 0; kb <= qb; kb++) {
        __syncthreads();  // PV of previous iter done before overwriting KVs
        {
            const float* p = kg + (size_t)lr * S_LEN + kb * 64 + lc;
            *(float4*)&KVs[lr][lc + 0]  = *(const float4*)(p + 0);
            *(float4*)&KVs[lr][lc + 4]  = *(const float4*)(p + 4);
            *(float4*)&KVs[lr][lc + 8]  = *(const float4*)(p + 8);
            *(float4*)&KVs[lr][lc + 12] = *(const float4*)(p + 12);
        }
        __syncthreads();

        float sc[4][4];
#pragma unroll
        for (int i = 0; i < 4; i++)
#pragma unroll
            for (int j = 0; j < 4; j++) sc[i][j] = 0.f;

#pragma unroll 16
        for (int d = 0; d < 64; d++) {
            float4 qf = *(const float4*)&Qs[d][ty * 4];
            float4 kf = *(const float4*)&KVs[d][tx * 4];
            float qa[4] = {qf.x, qf.y, qf.z, qf.w};
            float ka[4] = {kf.x, kf.y, kf.z, kf.w};
#pragma unroll
            for (int i = 0; i < 4; i++)
#pragma unroll
                for (int j = 0; j < 4; j++)
                    sc[i][j] = fmaf(qa[i], ka[j], sc[i][j]);
        }

        // scale + causal mask (only the diagonal block needs masking)
        int qi0 = qb * 64 + ty * 4;
        int kj0 = kb * 64 + tx * 4;
#pragma unroll
        for (int i = 0; i < 4; i++)
#pragma unroll
            for (int j = 0; j < 4; j++) {
                float v = sc[i][j] * 0.125f;
                sc[i][j] = (kb == qb && (kj0 + j) > (qi0 + i)) ? -1e30f : v;
            }

        __syncthreads();  // all K reads from KVs done

        // issue V global loads early (overlap with softmax math)
        const float* vp = vg + (size_t)(kb * 64 + lr) * HEAD_DIM + lc;
        float4 w0 = *(const float4*)(vp + 0);
        float4 w1 = *(const float4*)(vp + 4);
        float4 w2 = *(const float4*)(vp + 8);
        float4 w3 = *(const float4*)(vp + 12);

        // online softmax per query row (row spread across 16 tx lanes)
#pragma unroll
        for (int i = 0; i < 4; i++) {
            float rmax = fmaxf(fmaxf(sc[i][0], sc[i][1]),
                               fmaxf(sc[i][2], sc[i][3]));
#pragma unroll
            for (int ofs = 8; ofs > 0; ofs >>= 1)
                rmax = fmaxf(rmax, __shfl_xor_sync(0xffffffffu, rmax, ofs, 16));
            float mn = fmaxf(m[i], rmax);
            float corr = __expf(m[i] - mn);
            l[i] *= corr;
#pragma unroll
            for (int j = 0; j < 4; j++) o[i][j] *= corr;
            float rs = 0.f;
#pragma unroll
            for (int j = 0; j < 4; j++) {
                float pv = __expf(sc[i][j] - mn);
                sc[i][j] = pv;
                rs += pv;
            }
#pragma unroll
            for (int ofs = 8; ofs > 0; ofs >>= 1)
                rs += __shfl_xor_sync(0xffffffffu, rs, ofs, 16);
            l[i] += rs;
            m[i] = mn;
            // transposed store with row rotation: (i + j/4) & 63 kills the
            // 16-way bank conflict of a naive [j][i] store (j/4 == tx here)
#pragma unroll
            for (int j = 0; j < 4; j++)
                Ps[(tx * 4 + j) * 64 + ((ty * 4 + i + tx) & 63)] = sc[i][j];
        }

        // V into smem (KVs now [j][d])
        *(float4*)&KVs[lr][lc + 0]  = w0;
        *(float4*)&KVs[lr][lc + 4]  = w1;
        *(float4*)&KVs[lr][lc + 8]  = w2;
        *(float4*)&KVs[lr][lc + 12] = w3;
        __syncthreads();

        // PV: o[i][d] += P[i][j] * V[j][d]
#pragma unroll 8
        for (int j = 0; j < 64; j++) {
            float4 vf = *(const float4*)&KVs[j][tx * 4];
            int rot = j >> 2;
            float p0 = Ps[j * 64 + ((ty * 4 + 0 + rot) & 63)];
            float p1 = Ps[j * 64 + ((ty * 4 + 1 + rot) & 63)];
            float p2 = Ps[j * 64 + ((ty * 4 + 2 + rot) & 63)];
            float p3 = Ps[j * 64 + ((ty * 4 + 3 + rot) & 63)];
            o[0][0] = fmaf(p0, vf.x, o[0][0]);
            o[0][1] = fmaf(p0, vf.y, o[0][1]);
            o[0][2] = fmaf(p0, vf.z, o[0][2]);
            o[0][3] = fmaf(p0, vf.w, o[0][3]);
            o[1][0] = fmaf(p1, vf.x, o[1][0]);
            o[1][1] = fmaf(p1, vf.y, o[1][1]);
            o[1][2] = fmaf(p1, vf.z, o[1][2]);
            o[1][3] = fmaf(p1, vf.w, o[1][3]);
            o[2][0] = fmaf(p2, vf.x, o[2][0]);
            o[2][1] = fmaf(p2, vf.y, o[2][1]);
            o[2][2] = fmaf(p2, vf.z, o[2][2]);
            o[2][3] = fmaf(p2, vf.w, o[2][3]);
            o[3][0] = fmaf(p3, vf.x, o[3][0]);
            o[3][1] = fmaf(p3, vf.y, o[3][1]);
            o[3][2] = fmaf(p3, vf.z, o[3][2]);
            o[3][3] = fmaf(p3, vf.w, o[3][3]);
        }
    }

#pragma unroll
    for (int i = 0; i < 4; i++) {
        float inv = 1.f / l[i];
        size_t ro = (size_t)(qb * 64 + ty * 4 + i) * D_MODEL +
                    h * HEAD_DIM + tx * 4;
#pragma unroll
        for (int j = 0; j < 4; j++)
            g_at[ro + j] = o[i][j] * inv;
    }
}

extern "C" void kernel_launch(void* const* d_in, const int* in_sizes, int n_in,
                              void* d_out, int out_size)
{
    // metadata order: x, start_pos, freqs_cos, freqs_sin, mask,
    //                 wq_w, wq_b, wk_w, wk_b, wv_w, wv_b, wo_w, wo_b
    const float* x    = (const float*)d_in[0];
    const float* fcos = (const float*)d_in[2];
    const float* fsin = (const float*)d_in[3];
    // mask (d_in[4]) intentionally unused: causal mask applied analytically
    const float* wq  = (const float*)d_in[5];
    const float* wqb = (const float*)d_in[6];
    const float* wk  = (const float*)d_in[7];
    const float* wkb = (const float*)d_in[8];
    const float* wv  = (const float*)d_in[9];
    const float* wvb = (const float*)d_in[10];
    const float* wo  = (const float*)d_in[11];
    const float* wob = (const float*)d_in[12];
    float* out = (float*)d_out;

    dim3 gg(D_MODEL / 128, S_LEN / 128);
    gemm_k<MODE_Q><<<gg, 256>>>(x, wq, wqb, fcos, fsin, nullptr);
    gemm_k<MODE_K><<<gg, 256>>>(x, wk, wkb, fcos, fsin, nullptr);
    gemm_k<MODE_V><<<gg, 256>>>(x, wv, wvb, fcos, fsin, nullptr);
    attn_k<<<dim3(S_LEN / 64, N_HEADS), 256>>>();
    gemm_k<MODE_O><<<gg, 256>>>(nullptr, wo, wob, fcos, fsin, out);
}

// round 2
// speedup vs baseline: 1.0943x; 1.0943x over previous
#include <cuda_runtime.h>

#define S_LEN 4096
#define D_MODEL 1024
#define N_HEADS 16
#define HEAD_DIM 64
#define HALF_DIM 32

// Scratch (device globals; no allocations allowed)
__device__ float g_qt[N_HEADS * HEAD_DIM * S_LEN]; // [h][d][s]  (RoPE'd Q)
__device__ float g_kt[N_HEADS * HEAD_DIM * S_LEN]; // [h][d][s]  (RoPE'd K)
__device__ float g_vt[N_HEADS * S_LEN * HEAD_DIM]; // [h][s][d]
__device__ float g_at[S_LEN * D_MODEL];            // attention out [s][h*64+d]

enum { MODE_Q = 0, MODE_K = 1, MODE_V = 2, MODE_O = 3 };

// C = X[M,K] @ W^T (W is [N,K] row-major) + bias, with mode-specific epilogue.
// M = S_LEN, N = K = D_MODEL. BM=BN=128, BK=16, 256 threads, 8x8 per thread.
template <int MODE>
__global__ void __launch_bounds__(256) gemm_k(
    const float* __restrict__ Xin, const float* __restrict__ W,
    const float* __restrict__ bias, const float* __restrict__ fcos,
    const float* __restrict__ fsin, float* __restrict__ oout)
{
    const float* X = (MODE == MODE_O) ? (const float*)g_at : Xin;
    float* dst = (MODE == MODE_Q) ? g_qt
               : (MODE == MODE_K) ? g_kt
               : (MODE == MODE_V) ? g_vt
               : oout;

    __shared__ float As[16][132]; // [k][m], padded stride 132
    __shared__ float Bs[16][132]; // [k][n]

    const int K = D_MODEL;
    int bm = blockIdx.y * 128;
    int bn = blockIdx.x * 128;
    int tid = threadIdx.x;
    int tx = tid & 15;
    int ty = tid >> 4;
    int lr = tid >> 1;         // 0..127 : row within tile
    int lc = (tid & 1) << 3;   // 0 or 8 : k-column base

    const float* Ap = X + (size_t)(bm + lr) * K + lc;
    const float* Bp = W + (size_t)(bn + lr) * K + lc;

    float acc[8][8];
#pragma unroll
    for (int i = 0; i < 8; i++)
#pragma unroll
        for (int j = 0; j < 8; j++) acc[i][j] = 0.f;

    for (int k0 = 0; k0 < K; k0 += 16) {
        float4 a0 = *(const float4*)(Ap + k0);
        float4 a1 = *(const float4*)(Ap + k0 + 4);
        float4 b0 = *(const float4*)(Bp + k0);
        float4 b1 = *(const float4*)(Bp + k0 + 4);
        __syncthreads();
        As[lc + 0][lr] = a0.x; As[lc + 1][lr] = a0.y;
        As[lc + 2][lr] = a0.z; As[lc + 3][lr] = a0.w;
        As[lc + 4][lr] = a1.x; As[lc + 5][lr] = a1.y;
        As[lc + 6][lr] = a1.z; As[lc + 7][lr] = a1.w;
        Bs[lc + 0][lr] = b0.x; Bs[lc + 1][lr] = b0.y;
        Bs[lc + 2][lr] = b0.z; Bs[lc + 3][lr] = b0.w;
        Bs[lc + 4][lr] = b1.x; Bs[lc + 5][lr] = b1.y;
        Bs[lc + 6][lr] = b1.z; Bs[lc + 7][lr] = b1.w;
        __syncthreads();
#pragma unroll
        for (int kk = 0; kk < 16; kk++) {
            float af[8], bf[8];
            *(float4*)(af + 0) = *(const float4*)&As[kk][ty * 8];
            *(float4*)(af + 4) = *(const float4*)&As[kk][ty * 8 + 4];
            *(float4*)(bf + 0) = *(const float4*)&Bs[kk][tx * 8];
            *(float4*)(bf + 4) = *(const float4*)&Bs[kk][tx * 8 + 4];
#pragma unroll
            for (int i = 0; i < 8; i++)
#pragma unroll
                for (int j = 0; j < 8; j++)
                    acc[i][j] = fmaf(af[i], bf[j], acc[i][j]);
        }
    }

    int rbase = bm + ty * 8;
    int cbase = bn + tx * 8;

    if (MODE == MODE_O) {
#pragma unroll
        for (int i = 0; i < 8; i++) {
            size_t ro = (size_t)(rbase + i) * D_MODEL + cbase;
#pragma unroll
            for (int j = 0; j < 8; j++)
                dst[ro + j] = acc[i][j] + bias[cbase + j];
        }
    } else if (MODE == MODE_V) {
        int h = cbase >> 6;
        int d0 = cbase & 63;
#pragma unroll
        for (int i = 0; i < 8; i++) {
            size_t ro = (size_t)h * S_LEN * HEAD_DIM +
                        (size_t)(rbase + i) * HEAD_DIM + d0;
#pragma unroll
            for (int j = 0; j < 8; j++)
                dst[ro + j] = acc[i][j] + bias[cbase + j];
        }
    } else {
        int h = cbase >> 6;
        int d0 = cbase & 63;
        size_t hb = (size_t)h * HEAD_DIM * S_LEN;
#pragma unroll
        for (int i = 0; i < 8; i++) {
            int s = rbase + i;
#pragma unroll
            for (int jp = 0; jp < 4; jp++) {
                int d = d0 + jp * 2;
                float c  = fcos[s * HALF_DIM + (d >> 1)];
                float sn = fsin[s * HALF_DIM + (d >> 1)];
                float a0v = acc[i][jp * 2 + 0] + bias[cbase + jp * 2 + 0];
                float a1v = acc[i][jp * 2 + 1] + bias[cbase + jp * 2 + 1];
                dst[hb + (size_t)d * S_LEN + s]       = a0v * c - a1v * sn;
                dst[hb + (size_t)(d + 1) * S_LEN + s] = a0v * sn + a1v * c;
            }
        }
    }
}

// Flash attention, fp32. 128 queries x 128 keys per tile, 256 threads.
// Score micro-tile 8x8 (1 B LDS / FMA), PV micro-tile 8x4.
// Dynamic smem: Qs[64][132] | Ks[64][132] | Vs[128][68] | Ps[128][132]
#define ATTN_SMEM (2 * 64 * 132 * 4 + 128 * 68 * 4 + 128 * 132 * 4)

__global__ void __launch_bounds__(256, 1) attn_k()
{
    extern __shared__ float sm[];
    float (*Qs)[132] = (float(*)[132])sm;                     // [d][i]
    float (*Ks)[132] = (float(*)[132])(sm + 64 * 132);        // [d][j]
    float (*Vs)[68]  = (float(*)[68]) (sm + 2 * 64 * 132);    // [j][d]
    float (*Ps)[132] = (float(*)[132])(sm + 2 * 64 * 132 + 128 * 68); // [j][i]

    int qb = gridDim.x - 1 - blockIdx.x;  // longest blocks first
    int h = blockIdx.y;
    int tid = threadIdx.x;
    int tx = tid & 15;   // key group (score) / d group (PV)
    int ty = tid >> 4;   // query group

    const float* qg = g_qt + (size_t)h * HEAD_DIM * S_LEN;
    const float* kg = g_kt + (size_t)h * HEAD_DIM * S_LEN;
    const float* vg = g_vt + (size_t)h * S_LEN * HEAD_DIM;

    // Load Q tile [64 d][128 s]; thread: d = tid>>2, s-offset = (tid&3)*32
    {
        int d = tid >> 2;
        int so = (tid & 3) * 32;
        const float* p = qg + (size_t)d * S_LEN + qb * 128 + so;
#pragma unroll
        for (int v = 0; v < 8; v++)
            *(float4*)&Qs[d][so + v * 4] = *(const float4*)(p + v * 4);
    }

    float m[8], l[8], o[8][4];
#pragma unroll
    for (int i = 0; i < 8; i++) {
        m[i] = -1e30f;
        l[i] = 0.f;
#pragma unroll
        for (int j = 0; j < 4; j++) o[i][j] = 0.f;
    }

    for (int kb = 0; kb <= qb; kb++) {
        __syncthreads();  // prev PV done (Vs/Ps free), prev scores done (Ks free)
        {
            int d = tid >> 2;
            int so = (tid & 3) * 32;
            const float* p = kg + (size_t)d * S_LEN + kb * 128 + so;
#pragma unroll
            for (int v = 0; v < 8; v++)
                *(float4*)&Ks[d][so + v * 4] = *(const float4*)(p + v * 4);
        }
        {
            int j = tid >> 1;
            int dofs = (tid & 1) * 32;
            const float* p = vg + (size_t)(kb * 128 + j) * HEAD_DIM + dofs;
#pragma unroll
            for (int v = 0; v < 8; v++)
                *(float4*)&Vs[j][dofs + v * 4] = *(const float4*)(p + v * 4);
        }
        __syncthreads();

        // ---- scores: sc[i][j] = sum_d Q[d][ty*8+i] * K[d][tx*8+j]
        float sc[8][8];
#pragma unroll
        for (int i = 0; i < 8; i++)
#pragma unroll
            for (int j = 0; j < 8; j++) sc[i][j] = 0.f;

#pragma unroll 8
        for (int d = 0; d < 64; d++) {
            float qa[8], ka[8];
            *(float4*)(qa + 0) = *(const float4*)&Qs[d][ty * 8];
            *(float4*)(qa + 4) = *(const float4*)&Qs[d][ty * 8 + 4];
            *(float4*)(ka + 0) = *(const float4*)&Ks[d][tx * 8];
            *(float4*)(ka + 4) = *(const float4*)&Ks[d][tx * 8 + 4];
#pragma unroll
            for (int i = 0; i < 8; i++)
#pragma unroll
                for (int j = 0; j < 8; j++)
                    sc[i][j] = fmaf(qa[i], ka[j], sc[i][j]);
        }

        // scale + causal mask (diagonal tile only)
        if (kb == qb) {
            int qi0 = ty * 8;
            int kj0 = tx * 8;
#pragma unroll
            for (int i = 0; i < 8; i++)
#pragma unroll
                for (int j = 0; j < 8; j++)
                    sc[i][j] = (kj0 + j > qi0 + i) ? -1e30f : sc[i][j] * 0.125f;
        } else {
#pragma unroll
            for (int i = 0; i < 8; i++)
#pragma unroll
                for (int j = 0; j < 8; j++)
                    sc[i][j] *= 0.125f;
        }

        // ---- online softmax (row spread across 16 tx lanes)
#pragma unroll
        for (int i = 0; i < 8; i++) {
            float rmax = sc[i][0];
#pragma unroll
            for (int j = 1; j < 8; j++) rmax = fmaxf(rmax, sc[i][j]);
#pragma unroll
            for (int ofs = 8; ofs > 0; ofs >>= 1)
                rmax = fmaxf(rmax, __shfl_xor_sync(0xffffffffu, rmax, ofs, 16));
            float mn = fmaxf(m[i], rmax);
            float corr = __expf(m[i] - mn);
            l[i] *= corr;
#pragma unroll
            for (int j = 0; j < 4; j++) o[i][j] *= corr;
            float rs = 0.f;
#pragma unroll
            for (int j = 0; j < 8; j++) {
                float pv = __expf(sc[i][j] - mn);
                sc[i][j] = pv;
                rs += pv;
            }
#pragma unroll
            for (int ofs = 8; ofs > 0; ofs >>= 1)
                rs += __shfl_xor_sync(0xffffffffu, rs, ofs, 16);
            l[i] += rs;
            m[i] = mn;
        }

        // store P transposed: Ps[j][i] (row stride 132 kills bank conflicts)
#pragma unroll
        for (int jj = 0; jj < 8; jj++) {
            float4 p0 = make_float4(sc[0][jj], sc[1][jj], sc[2][jj], sc[3][jj]);
            float4 p1 = make_float4(sc[4][jj], sc[5][jj], sc[6][jj], sc[7][jj]);
            *(float4*)&Ps[tx * 8 + jj][ty * 8 + 0] = p0;
            *(float4*)&Ps[tx * 8 + jj][ty * 8 + 4] = p1;
        }
        __syncthreads();

        // ---- PV: o[i][d] += P[j][i] * V[j][d], d = tx*4..tx*4+3
#pragma unroll 4
        for (int j = 0; j < 128; j++) {
            float pa[8];
            *(float4*)(pa + 0) = *(const float4*)&Ps[j][ty * 8];
            *(float4*)(pa + 4) = *(const float4*)&Ps[j][ty * 8 + 4];
            float4 vf = *(const float4*)&Vs[j][tx * 4];
#pragma unroll
            for (int i = 0; i < 8; i++) {
                o[i][0] = fmaf(pa[i], vf.x, o[i][0]);
                o[i][1] = fmaf(pa[i], vf.y, o[i][1]);
                o[i][2] = fmaf(pa[i], vf.z, o[i][2]);
                o[i][3] = fmaf(pa[i], vf.w, o[i][3]);
            }
        }
    }

#pragma unroll
    for (int i = 0; i < 8; i++) {
        float inv = 1.f / l[i];
        size_t ro = (size_t)(qb * 128 + ty * 8 + i) * D_MODEL +
                    h * HEAD_DIM + tx * 4;
#pragma unroll
        for (int j = 0; j < 4; j++)
            g_at[ro + j] = o[i][j] * inv;
    }
}

extern "C" void kernel_launch(void* const* d_in, const int* in_sizes, int n_in,
                              void* d_out, int out_size)
{
    const float* x    = (const float*)d_in[0];
    const float* fcos = (const float*)d_in[2];
    const float* fsin = (const float*)d_in[3];
    const float* wq  = (const float*)d_in[5];
    const float* wqb = (const float*)d_in[6];
    const float* wk  = (const float*)d_in[7];
    const float* wkb = (const float*)d_in[8];
    const float* wv  = (const float*)d_in[9];
    const float* wvb = (const float*)d_in[10];
    const float* wo  = (const float*)d_in[11];
    const float* wob = (const float*)d_in[12];
    float* out = (float*)d_out;

    static bool attr_set = false;
    if (!attr_set) {
        cudaFuncSetAttribute(attn_k,
                             cudaFuncAttributeMaxDynamicSharedMemorySize,
                             ATTN_SMEM);
        attr_set = true;
    }

    dim3 gg(D_MODEL / 128, S_LEN / 128);
    gemm_k<MODE_Q><<<gg, 256>>>(x, wq, wqb, fcos, fsin, nullptr);
    gemm_k<MODE_K><<<gg, 256>>>(x, wk, wkb, fcos, fsin, nullptr);
    gemm_k<MODE_V><<<gg, 256>>>(x, wv, wvb, fcos, fsin, nullptr);
    attn_k<<<dim3(S_LEN / 128, N_HEADS), 256, ATTN_SMEM>>>();
    gemm_k<MODE_O><<<gg, 256>>>(nullptr, wo, wob, fcos, fsin, out);
}

// round 4
// speedup vs baseline: 1.3933x; 1.2732x over previous
#include <cuda_runtime.h>
#include <cuda_bf16.h>
#include <cstdint>

#define S_LEN 4096
#define D_MODEL 1024
#define N_HEADS 16
#define HEAD_DIM 64
#define HALF_DIM 32

// Scratch (device globals; no allocations allowed)
__device__ float g_qt[N_HEADS * HEAD_DIM * S_LEN]; // [h][d][s]  (RoPE'd Q)
__device__ float g_kt[N_HEADS * HEAD_DIM * S_LEN]; // [h][d][s]  (RoPE'd K)
__device__ float g_vt[N_HEADS * S_LEN * HEAD_DIM]; // [h][s][d]
__device__ float g_at[S_LEN * D_MODEL];            // attention out [s][h*64+d]

enum { MODE_Q = 0, MODE_K = 1, MODE_V = 2, MODE_O = 3 };

// ---------------- mma.sync helpers (PTX baseline, legal on sm_103) ---------
__device__ __forceinline__ uint32_t smem_u32(const void* p) {
    uint32_t a;
    asm("{ .reg .u64 t; cvta.to.shared.u64 t, %1; cvt.u32.u64 %0, t; }"
        : "=r"(a) : "l"(p));
    return a;
}

__device__ __forceinline__ void ldsm_x4(uint32_t* r, uint32_t addr) {
    asm volatile("ldmatrix.sync.aligned.m8n8.x4.shared.b16 {%0,%1,%2,%3}, [%4];"
                 : "=r"(r[0]), "=r"(r[1]), "=r"(r[2]), "=r"(r[3]) : "r"(addr));
}
__device__ __forceinline__ void ldsm_x2(uint32_t* r, uint32_t addr) {
    asm volatile("ldmatrix.sync.aligned.m8n8.x2.shared.b16 {%0,%1}, [%2];"
                 : "=r"(r[0]), "=r"(r[1]) : "r"(addr));
}

__device__ __forceinline__ void mma_bf16(float* c, const uint32_t* a,
                                         const uint32_t* b) {
    asm volatile(
        "mma.sync.aligned.m16n8k16.row.col.f32.bf16.bf16.f32 "
        "{%0,%1,%2,%3}, {%4,%5,%6,%7}, {%8,%9}, {%0,%1,%2,%3};"
        : "+f"(c[0]), "+f"(c[1]), "+f"(c[2]), "+f"(c[3])
        : "r"(a[0]), "r"(a[1]), "r"(a[2]), "r"(a[3]), "r"(b[0]), "r"(b[1]));
}

__device__ __forceinline__ uint32_t pk_bf2(__nv_bfloat16 a, __nv_bfloat16 b) {
    __nv_bfloat162 t = __halves2bfloat162(a, b);
    return *reinterpret_cast<uint32_t*>(&t);
}

#define LDT 40  // bf16 row stride in smem tiles (80B -> conflict-free ldmatrix)

// Convert 16 consecutive f32 to hi/lo bf16 and store to smem tiles.
__device__ __forceinline__ void cvt_store(uint32_t hi, uint32_t lo,
                                          int row, int kc, const float4* v) {
    uint32_t off = (uint32_t)(row * LDT + kc) * 2u;
    uint32_t ph[8], pl[8];
#pragma unroll
    for (int u = 0; u < 4; u++) {
        float4 f = v[u];
        __nv_bfloat16 h0 = __float2bfloat16_rn(f.x);
        __nv_bfloat16 h1 = __float2bfloat16_rn(f.y);
        __nv_bfloat16 h2 = __float2bfloat16_rn(f.z);
        __nv_bfloat16 h3 = __float2bfloat16_rn(f.w);
        __nv_bfloat16 l0 = __float2bfloat16_rn(f.x - __bfloat162float(h0));
        __nv_bfloat16 l1 = __float2bfloat16_rn(f.y - __bfloat162float(h1));
        __nv_bfloat16 l2 = __float2bfloat16_rn(f.z - __bfloat162float(h2));
        __nv_bfloat16 l3 = __float2bfloat16_rn(f.w - __bfloat162float(h3));
        ph[2 * u] = pk_bf2(h0, h1); ph[2 * u + 1] = pk_bf2(h2, h3);
        pl[2 * u] = pk_bf2(l0, l1); pl[2 * u + 1] = pk_bf2(l2, l3);
    }
    asm volatile("st.shared.v4.b32 [%0], {%1,%2,%3,%4};"
                 :: "r"(hi + off), "r"(ph[0]), "r"(ph[1]), "r"(ph[2]), "r"(ph[3])
                 : "memory");
    asm volatile("st.shared.v4.b32 [%0], {%1,%2,%3,%4};"
                 :: "r"(hi + off + 16u), "r"(ph[4]), "r"(ph[5]), "r"(ph[6]), "r"(ph[7])
                 : "memory");
    asm volatile("st.shared.v4.b32 [%0], {%1,%2,%3,%4};"
                 :: "r"(lo + off), "r"(pl[0]), "r"(pl[1]), "r"(pl[2]), "r"(pl[3])
                 : "memory");
    asm volatile("st.shared.v4.b32 [%0], {%1,%2,%3,%4};"
                 :: "r"(lo + off + 16u), "r"(pl[4]), "r"(pl[5]), "r"(pl[6]), "r"(pl[7])
                 : "memory");
}

__device__ __forceinline__ uint32_t addrA(uint32_t base, int m0, int k0, int lane) {
    int r = m0 + (lane & 15);
    int c = k0 + ((lane >> 4) << 3);
    return base + (uint32_t)(r * LDT + c) * 2u;
}
__device__ __forceinline__ uint32_t addrB(uint32_t base, int n0, int k0, int lane) {
    int r = n0 + (lane & 7);
    int c = k0 + (((lane >> 3) & 1) << 3);
    return base + (uint32_t)(r * LDT + c) * 2u;
}

// ------------------- tensor-core GEMM: C = X @ W^T + bias ------------------
// 128x128 CTA tile, 8 warps (2M x 4N), warp tile 64x32, BK=32, split-bf16.
template <int MODE>
__global__ void __launch_bounds__(256, 1) gemm_tc(
    const float* __restrict__ Xin, const float* __restrict__ W,
    const float* __restrict__ bias, const float* __restrict__ fcos,
    const float* __restrict__ fsin, float* __restrict__ oout)
{
    __shared__ __nv_bfloat16 sAhi[128 * LDT], sAlo[128 * LDT];
    __shared__ __nv_bfloat16 sBhi[128 * LDT], sBlo[128 * LDT];

    const float* X = (MODE == MODE_O) ? (const float*)g_at : Xin;
    float* dst = (MODE == MODE_Q) ? g_qt
               : (MODE == MODE_K) ? g_kt
               : (MODE == MODE_V) ? g_vt
               : oout;

    uint32_t aAhi = smem_u32(sAhi), aAlo = smem_u32(sAlo);
    uint32_t aBhi = smem_u32(sBhi), aBlo = smem_u32(sBlo);

    int tid = threadIdx.x, wid = tid >> 5, lane = tid & 31;
    int wm = wid >> 2, wn = wid & 3;
    int m0 = wm * 64, n0 = wn * 32;
    int bm = blockIdx.y * 128, bn = blockIdx.x * 128;

    int lrow = tid >> 1, lks = (tid & 1) * 16;
    const float* Ap = X + (size_t)(bm + lrow) * D_MODEL + lks;
    const float* Bp = W + (size_t)(bn + lrow) * D_MODEL + lks;

    float4 av[4], bv[4];
#pragma unroll
    for (int v = 0; v < 4; v++) {
        av[v] = *(const float4*)(Ap + v * 4);
        bv[v] = *(const float4*)(Bp + v * 4);
    }

    float acc[4][4][4];
#pragma unroll
    for (int i = 0; i < 4; i++)
#pragma unroll
        for (int j = 0; j < 4; j++)
#pragma unroll
            for (int e = 0; e < 4; e++) acc[i][j][e] = 0.f;

    for (int c = 0; c < 32; c++) {
        cvt_store(aAhi, aAlo, lrow, lks, av);
        cvt_store(aBhi, aBlo, lrow, lks, bv);
        __syncthreads();
        if (c < 31) {
            const float* ap = Ap + (c + 1) * 32;
            const float* bp = Bp + (c + 1) * 32;
#pragma unroll
            for (int v = 0; v < 4; v++) {
                av[v] = *(const float4*)(ap + v * 4);
                bv[v] = *(const float4*)(bp + v * 4);
            }
        }
#pragma unroll
        for (int ks = 0; ks < 2; ks++) {
            int k0 = ks * 16;
            uint32_t bh[4][2], bl[4][2];
#pragma unroll
            for (int nt = 0; nt < 4; nt++) {
                ldsm_x2(bh[nt], addrB(aBhi, n0 + nt * 8, k0, lane));
                ldsm_x2(bl[nt], addrB(aBlo, n0 + nt * 8, k0, lane));
            }
#pragma unroll
            for (int mt = 0; mt < 4; mt++) {
                uint32_t ah[4], al[4];
                ldsm_x4(ah, addrA(aAhi, m0 + mt * 16, k0, lane));
                ldsm_x4(al, addrA(aAlo, m0 + mt * 16, k0, lane));
#pragma unroll
                for (int nt = 0; nt < 4; nt++) {
                    mma_bf16(acc[mt][nt], ah, bh[nt]);
                    mma_bf16(acc[mt][nt], ah, bl[nt]);
                    mma_bf16(acc[mt][nt], al, bh[nt]);
                }
            }
        }
        __syncthreads();
    }

    // ---------------- epilogue ----------------
    int rq = lane >> 2;          // fragment row within m16
    int cq = (lane & 3) * 2;     // fragment col pair within n8
#pragma unroll
    for (int mt = 0; mt < 4; mt++) {
#pragma unroll
        for (int nt = 0; nt < 4; nt++) {
            int r0 = bm + m0 + mt * 16 + rq;   // global rows r0, r0+8
            int cg = bn + n0 + nt * 8 + cq;    // global col (even)
            float b0 = bias[cg], b1 = bias[cg + 1];
            float v00 = acc[mt][nt][0] + b0, v01 = acc[mt][nt][1] + b1;
            float v10 = acc[mt][nt][2] + b0, v11 = acc[mt][nt][3] + b1;
            if (MODE == MODE_O) {
                *(float2*)(dst + (size_t)r0 * D_MODEL + cg) =
                    make_float2(v00, v01);
                *(float2*)(dst + (size_t)(r0 + 8) * D_MODEL + cg) =
                    make_float2(v10, v11);
            } else if (MODE == MODE_V) {
                int h = cg >> 6, d = cg & 63;
                float* hp = dst + (size_t)h * S_LEN * HEAD_DIM + d;
                *(float2*)(hp + (size_t)r0 * HEAD_DIM) = make_float2(v00, v01);
                *(float2*)(hp + (size_t)(r0 + 8) * HEAD_DIM) = make_float2(v10, v11);
            } else {
                int h = cg >> 6, d = cg & 63;
                float* hp = dst + (size_t)h * HEAD_DIM * S_LEN;
                float c0 = fcos[(size_t)r0 * HALF_DIM + (d >> 1)];
                float s0 = fsin[(size_t)r0 * HALF_DIM + (d >> 1)];
                float c1 = fcos[(size_t)(r0 + 8) * HALF_DIM + (d >> 1)];
                float s1 = fsin[(size_t)(r0 + 8) * HALF_DIM + (d >> 1)];
                hp[(size_t)d * S_LEN + r0]           = v00 * c0 - v01 * s0;
                hp[(size_t)(d + 1) * S_LEN + r0]     = v00 * s0 + v01 * c0;
                hp[(size_t)d * S_LEN + r0 + 8]       = v10 * c1 - v11 * s1;
                hp[(size_t)(d + 1) * S_LEN + r0 + 8] = v10 * s1 + v11 * c1;
            }
        }
    }
}

// ------------------- flash attention (fp32 SIMT, unchanged) ----------------
#define ATTN_SMEM (2 * 64 * 132 * 4 + 128 * 68 * 4 + 128 * 132 * 4)

__global__ void __launch_bounds__(256, 1) attn_k()
{
    extern __shared__ float sm[];
    float (*Qs)[132] = (float(*)[132])sm;                     // [d][i]
    float (*Ks)[132] = (float(*)[132])(sm + 64 * 132);        // [d][j]
    float (*Vs)[68]  = (float(*)[68]) (sm + 2 * 64 * 132);    // [j][d]
    float (*Ps)[132] = (float(*)[132])(sm + 2 * 64 * 132 + 128 * 68); // [j][i]

    int qb = gridDim.x - 1 - blockIdx.x;
    int h = blockIdx.y;
    int tid = threadIdx.x;
    int tx = tid & 15;
    int ty = tid >> 4;

    const float* qg = g_qt + (size_t)h * HEAD_DIM * S_LEN;
    const float* kg = g_kt + (size_t)h * HEAD_DIM * S_LEN;
    const float* vg = g_vt + (size_t)h * S_LEN * HEAD_DIM;

    {
        int d = tid >> 2;
        int so = (tid & 3) * 32;
        const float* p = qg + (size_t)d * S_LEN + qb * 128 + so;
#pragma unroll
        for (int v = 0; v < 8; v++)
            *(float4*)&Qs[d][so + v * 4] = *(const float4*)(p + v * 4);
    }

    float m[8], l[8], o[8][4];
#pragma unroll
    for (int i = 0; i < 8; i++) {
        m[i] = -1e30f;
        l[i] = 0.f;
#pragma unroll
        for (int j = 0; j < 4; j++) o[i][j] = 0.f;
    }

    for (int kb = 0; kb <= qb; kb++) {
        __syncthreads();
        {
            int d = tid >> 2;
            int so = (tid & 3) * 32;
            const float* p = kg + (size_t)d * S_LEN + kb * 128 + so;
#pragma unroll
            for (int v = 0; v < 8; v++)
                *(float4*)&Ks[d][so + v * 4] = *(const float4*)(p + v * 4);
        }
        {
            int j = tid >> 1;
            int dofs = (tid & 1) * 32;
            const float* p = vg + (size_t)(kb * 128 + j) * HEAD_DIM + dofs;
#pragma unroll
            for (int v = 0; v < 8; v++)
                *(float4*)&Vs[j][dofs + v * 4] = *(const float4*)(p + v * 4);
        }
        __syncthreads();

        float sc[8][8];
#pragma unroll
        for (int i = 0; i < 8; i++)
#pragma unroll
            for (int j = 0; j < 8; j++) sc[i][j] = 0.f;

#pragma unroll 8
        for (int d = 0; d < 64; d++) {
            float qa[8], ka[8];
            *(float4*)(qa + 0) = *(const float4*)&Qs[d][ty * 8];
            *(float4*)(qa + 4) = *(const float4*)&Qs[d][ty * 8 + 4];
            *(float4*)(ka + 0) = *(const float4*)&Ks[d][tx * 8];
            *(float4*)(ka + 4) = *(const float4*)&Ks[d][tx * 8 + 4];
#pragma unroll
            for (int i = 0; i < 8; i++)
#pragma unroll
                for (int j = 0; j < 8; j++)
                    sc[i][j] = fmaf(qa[i], ka[j], sc[i][j]);
        }

        if (kb == qb) {
            int qi0 = ty * 8;
            int kj0 = tx * 8;
#pragma unroll
            for (int i = 0; i < 8; i++)
#pragma unroll
                for (int j = 0; j < 8; j++)
                    sc[i][j] = (kj0 + j > qi0 + i) ? -1e30f : sc[i][j] * 0.125f;
        } else {
#pragma unroll
            for (int i = 0; i < 8; i++)
#pragma unroll
                for (int j = 0; j < 8; j++)
                    sc[i][j] *= 0.125f;
        }

#pragma unroll
        for (int i = 0; i < 8; i++) {
            float rmax = sc[i][0];
#pragma unroll
            for (int j = 1; j < 8; j++) rmax = fmaxf(rmax, sc[i][j]);
#pragma unroll
            for (int ofs = 8; ofs > 0; ofs >>= 1)
                rmax = fmaxf(rmax, __shfl_xor_sync(0xffffffffu, rmax, ofs, 16));
            float mn = fmaxf(m[i], rmax);
            float corr = __expf(m[i] - mn);
            l[i] *= corr;
#pragma unroll
            for (int j = 0; j < 4; j++) o[i][j] *= corr;
            float rs = 0.f;
#pragma unroll
            for (int j = 0; j < 8; j++) {
                float pv = __expf(sc[i][j] - mn);
                sc[i][j] = pv;
                rs += pv;
            }
#pragma unroll
            for (int ofs = 8; ofs > 0; ofs >>= 1)
                rs += __shfl_xor_sync(0xffffffffu, rs, ofs, 16);
            l[i] += rs;
            m[i] = mn;
        }

#pragma unroll
        for (int jj = 0; jj < 8; jj++) {
            float4 p0 = make_float4(sc[0][jj], sc[1][jj], sc[2][jj], sc[3][jj]);
            float4 p1 = make_float4(sc[4][jj], sc[5][jj], sc[6][jj], sc[7][jj]);
            *(float4*)&Ps[tx * 8 + jj][ty * 8 + 0] = p0;
            *(float4*)&Ps[tx * 8 + jj][ty * 8 + 4] = p1;
        }
        __syncthreads();

#pragma unroll 4
        for (int j = 0; j < 128; j++) {
            float pa[8];
            *(float4*)(pa + 0) = *(const float4*)&Ps[j][ty * 8];
            *(float4*)(pa + 4) = *(const float4*)&Ps[j][ty * 8 + 4];
            float4 vf = *(const float4*)&Vs[j][tx * 4];
#pragma unroll
            for (int i = 0; i < 8; i++) {
                o[i][0] = fmaf(pa[i], vf.x, o[i][0]);
                o[i][1] = fmaf(pa[i], vf.y, o[i][1]);
                o[i][2] = fmaf(pa[i], vf.z, o[i][2]);
                o[i][3] = fmaf(pa[i], vf.w, o[i][3]);
            }
        }
    }

#pragma unroll
    for (int i = 0; i < 8; i++) {
        float inv = 1.f / l[i];
        size_t ro = (size_t)(qb * 128 + ty * 8 + i) * D_MODEL +
                    h * HEAD_DIM + tx * 4;
#pragma unroll
        for (int j = 0; j < 4; j++)
            g_at[ro + j] = o[i][j] * inv;
    }
}

extern "C" void kernel_launch(void* const* d_in, const int* in_sizes, int n_in,
                              void* d_out, int out_size)
{
    const float* x    = (const float*)d_in[0];
    const float* fcos = (const float*)d_in[2];
    const float* fsin = (const float*)d_in[3];
    const float* wq  = (const float*)d_in[5];
    const float* wqb = (const float*)d_in[6];
    const float* wk  = (const float*)d_in[7];
    const float* wkb = (const float*)d_in[8];
    const float* wv  = (const float*)d_in[9];
    const float* wvb = (const float*)d_in[10];
    const float* wo  = (const float*)d_in[11];
    const float* wob = (const float*)d_in[12];
    float* out = (float*)d_out;

    static bool attr_set = false;
    if (!attr_set) {
        cudaFuncSetAttribute(attn_k,
                             cudaFuncAttributeMaxDynamicSharedMemorySize,
                             ATTN_SMEM);
        attr_set = true;
    }

    dim3 gg(D_MODEL / 128, S_LEN / 128);
    gemm_tc<MODE_Q><<<gg, 256>>>(x, wq, wqb, fcos, fsin, nullptr);
    gemm_tc<MODE_K><<<gg, 256>>>(x, wk, wkb, fcos, fsin, nullptr);
    gemm_tc<MODE_V><<<gg, 256>>>(x, wv, wvb, fcos, fsin, nullptr);
    attn_k<<<dim3(S_LEN / 128, N_HEADS), 256, ATTN_SMEM>>>();
    gemm_tc<MODE_O><<<gg, 256>>>(nullptr, wo, wob, fcos, fsin, out);
}

// round 5
// speedup vs baseline: 2.8487x; 2.0446x over previous
#include <cuda_runtime.h>
#include <cuda_bf16.h>
#include <cstdint>

#define S_LEN 4096
#define D_MODEL 1024
#define N_HEADS 16
#define HEAD_DIM 64
#define HALF_DIM 32

// Scratch (device globals; no allocations allowed)
__device__ float g_q[N_HEADS * S_LEN * HEAD_DIM];  // [h][s][d]  (RoPE'd, pre-scaled not)
__device__ float g_k[N_HEADS * S_LEN * HEAD_DIM];  // [h][s][d]  (RoPE'd)
__device__ float g_v[N_HEADS * HEAD_DIM * S_LEN];  // [h][d][s]
__device__ float g_at[S_LEN * D_MODEL];            // attention out [s][h*64+d]

enum { MODE_Q = 0, MODE_K = 1, MODE_V = 2, MODE_O = 3 };

// ---------------- mma.sync helpers (PTX baseline, legal on sm_103) ---------
__device__ __forceinline__ uint32_t smem_u32(const void* p) {
    uint32_t a;
    asm("{ .reg .u64 t; cvta.to.shared.u64 t, %1; cvt.u32.u64 %0, t; }"
        : "=r"(a) : "l"(p));
    return a;
}

__device__ __forceinline__ void ldsm_x4(uint32_t* r, uint32_t addr) {
    asm volatile("ldmatrix.sync.aligned.m8n8.x4.shared.b16 {%0,%1,%2,%3}, [%4];"
                 : "=r"(r[0]), "=r"(r[1]), "=r"(r[2]), "=r"(r[3]) : "r"(addr));
}
__device__ __forceinline__ void ldsm_x2(uint32_t* r, uint32_t addr) {
    asm volatile("ldmatrix.sync.aligned.m8n8.x2.shared.b16 {%0,%1}, [%2];"
                 : "=r"(r[0]), "=r"(r[1]) : "r"(addr));
}

__device__ __forceinline__ void mma_bf16(float* c, const uint32_t* a,
                                         const uint32_t* b) {
    asm volatile(
        "mma.sync.aligned.m16n8k16.row.col.f32.bf16.bf16.f32 "
        "{%0,%1,%2,%3}, {%4,%5,%6,%7}, {%8,%9}, {%0,%1,%2,%3};"
        : "+f"(c[0]), "+f"(c[1]), "+f"(c[2]), "+f"(c[3])
        : "r"(a[0]), "r"(a[1]), "r"(a[2]), "r"(a[3]), "r"(b[0]), "r"(b[1]));
}

__device__ __forceinline__ uint32_t pk_bf2(__nv_bfloat16 a, __nv_bfloat16 b) {
    __nv_bfloat162 t = __halves2bfloat162(a, b);
    return *reinterpret_cast<uint32_t*>(&t);
}

__device__ __forceinline__ void split2(float a, float b,
                                       uint32_t& hi, uint32_t& lo) {
    __nv_bfloat16 ha = __float2bfloat16_rn(a);
    __nv_bfloat16 hb = __float2bfloat16_rn(b);
    __nv_bfloat16 la = __float2bfloat16_rn(a - __bfloat162float(ha));
    __nv_bfloat16 lb = __float2bfloat16_rn(b - __bfloat162float(hb));
    hi = pk_bf2(ha, hb);
    lo = pk_bf2(la, lb);
}

__device__ __forceinline__ uint32_t addrA(uint32_t base, int m0, int k0,
                                          int lane, int ld) {
    int r = m0 + (lane & 15);
    int c = k0 + ((lane >> 4) << 3);
    return base + (uint32_t)(r * ld + c) * 2u;
}
__device__ __forceinline__ uint32_t addrB(uint32_t base, int n0, int k0,
                                          int lane, int ld) {
    int r = n0 + (lane & 7);
    int c = k0 + (((lane >> 3) & 1) << 3);
    return base + (uint32_t)(r * ld + c) * 2u;
}

#define LDT 40  // GEMM smem row stride (bf16)

// Convert 16 consecutive f32 to hi/lo bf16 and store to smem tiles.
__device__ __forceinline__ void cvt_store(uint32_t hi, uint32_t lo,
                                          int row, int kc, const float4* v) {
    uint32_t off = (uint32_t)(row * LDT + kc) * 2u;
    uint32_t ph[8], pl[8];
#pragma unroll
    for (int u = 0; u < 4; u++) {
        float4 f = v[u];
        split2(f.x, f.y, ph[2 * u], pl[2 * u]);
        split2(f.z, f.w, ph[2 * u + 1], pl[2 * u + 1]);
    }
    asm volatile("st.shared.v4.b32 [%0], {%1,%2,%3,%4};"
                 :: "r"(hi + off), "r"(ph[0]), "r"(ph[1]), "r"(ph[2]), "r"(ph[3])
                 : "memory");
    asm volatile("st.shared.v4.b32 [%0], {%1,%2,%3,%4};"
                 :: "r"(hi + off + 16u), "r"(ph[4]), "r"(ph[5]), "r"(ph[6]), "r"(ph[7])
                 : "memory");
    asm volatile("st.shared.v4.b32 [%0], {%1,%2,%3,%4};"
                 :: "r"(lo + off), "r"(pl[0]), "r"(pl[1]), "r"(pl[2]), "r"(pl[3])
                 : "memory");
    asm volatile("st.shared.v4.b32 [%0], {%1,%2,%3,%4};"
                 :: "r"(lo + off + 16u), "r"(pl[4]), "r"(pl[5]), "r"(pl[6]), "r"(pl[7])
                 : "memory");
}

// ------------------- tensor-core GEMM: C = X @ W^T + bias ------------------
// 128x128 CTA tile, 8 warps (2M x 4N), warp tile 64x32, BK=32, split-bf16.
template <int MODE>
__global__ void __launch_bounds__(256, 1) gemm_tc(
    const float* __restrict__ Xin, const float* __restrict__ W,
    const float* __restrict__ bias, const float* __restrict__ fcos,
    const float* __restrict__ fsin, float* __restrict__ oout)
{
    __shared__ __nv_bfloat16 sAhi[128 * LDT], sAlo[128 * LDT];
    __shared__ __nv_bfloat16 sBhi[128 * LDT], sBlo[128 * LDT];

    const float* X = (MODE == MODE_O) ? (const float*)g_at : Xin;
    float* dst = (MODE == MODE_Q) ? g_q
               : (MODE == MODE_K) ? g_k
               : (MODE == MODE_V) ? g_v
               : oout;

    uint32_t aAhi = smem_u32(sAhi), aAlo = smem_u32(sAlo);
    uint32_t aBhi = smem_u32(sBhi), aBlo = smem_u32(sBlo);

    int tid = threadIdx.x, wid = tid >> 5, lane = tid & 31;
    int wm = wid >> 2, wn = wid & 3;
    int m0 = wm * 64, n0 = wn * 32;
    int bm = blockIdx.y * 128, bn = blockIdx.x * 128;

    int lrow = tid >> 1, lks = (tid & 1) * 16;
    const float* Ap = X + (size_t)(bm + lrow) * D_MODEL + lks;
    const float* Bp = W + (size_t)(bn + lrow) * D_MODEL + lks;

    float4 av[4], bv[4];
#pragma unroll
    for (int v = 0; v < 4; v++) {
        av[v] = *(const float4*)(Ap + v * 4);
        bv[v] = *(const float4*)(Bp + v * 4);
    }

    float acc[4][4][4];
#pragma unroll
    for (int i = 0; i < 4; i++)
#pragma unroll
        for (int j = 0; j < 4; j++)
#pragma unroll
            for (int e = 0; e < 4; e++) acc[i][j][e] = 0.f;

    for (int c = 0; c < 32; c++) {
        cvt_store(aAhi, aAlo, lrow, lks, av);
        cvt_store(aBhi, aBlo, lrow, lks, bv);
        __syncthreads();
        if (c < 31) {
            const float* ap = Ap + (c + 1) * 32;
            const float* bp = Bp + (c + 1) * 32;
#pragma unroll
            for (int v = 0; v < 4; v++) {
                av[v] = *(const float4*)(ap + v * 4);
                bv[v] = *(const float4*)(bp + v * 4);
            }
        }
#pragma unroll
        for (int ks = 0; ks < 2; ks++) {
            int k0 = ks * 16;
            uint32_t bh[4][2], bl[4][2];
#pragma unroll
            for (int nt = 0; nt < 4; nt++) {
                ldsm_x2(bh[nt], addrB(aBhi, n0 + nt * 8, k0, lane, LDT));
                ldsm_x2(bl[nt], addrB(aBlo, n0 + nt * 8, k0, lane, LDT));
            }
#pragma unroll
            for (int mt = 0; mt < 4; mt++) {
                uint32_t ah[4], al[4];
                ldsm_x4(ah, addrA(aAhi, m0 + mt * 16, k0, lane, LDT));
                ldsm_x4(al, addrA(aAlo, m0 + mt * 16, k0, lane, LDT));
#pragma unroll
                for (int nt = 0; nt < 4; nt++) {
                    mma_bf16(acc[mt][nt], ah, bh[nt]);
                    mma_bf16(acc[mt][nt], ah, bl[nt]);
                    mma_bf16(acc[mt][nt], al, bh[nt]);
                }
            }
        }
        __syncthreads();
    }

    // ---------------- epilogue ----------------
    int rq = lane >> 2;          // fragment row within m16
    int cq = (lane & 3) * 2;     // fragment col pair within n8
#pragma unroll
    for (int mt = 0; mt < 4; mt++) {
#pragma unroll
        for (int nt = 0; nt < 4; nt++) {
            int r0 = bm + m0 + mt * 16 + rq;   // global rows r0, r0+8
            int cg = bn + n0 + nt * 8 + cq;    // global col (even)
            float b0 = bias[cg], b1 = bias[cg + 1];
            float v00 = acc[mt][nt][0] + b0, v01 = acc[mt][nt][1] + b1;
            float v10 = acc[mt][nt][2] + b0, v11 = acc[mt][nt][3] + b1;
            if (MODE == MODE_O) {
                *(float2*)(dst + (size_t)r0 * D_MODEL + cg) =
                    make_float2(v00, v01);
                *(float2*)(dst + (size_t)(r0 + 8) * D_MODEL + cg) =
                    make_float2(v10, v11);
            } else if (MODE == MODE_V) {
                // [h][d][s]
                int h = cg >> 6, d = cg & 63;
                float* hp = dst + ((size_t)h * HEAD_DIM + d) * S_LEN;
                hp[r0] = v00;              hp[S_LEN + r0] = v01;
                hp[r0 + 8] = v10;          hp[S_LEN + r0 + 8] = v11;
            } else {
                // Q/K: RoPE, write [h][s][d] (pair (d,d+1) is in-fragment!)
                int h = cg >> 6, d = cg & 63;
                float c0 = fcos[(size_t)r0 * HALF_DIM + (d >> 1)];
                float s0 = fsin[(size_t)r0 * HALF_DIM + (d >> 1)];
                float c1 = fcos[(size_t)(r0 + 8) * HALF_DIM + (d >> 1)];
                float s1 = fsin[(size_t)(r0 + 8) * HALF_DIM + (d >> 1)];
                float* hp = dst + ((size_t)h * S_LEN + r0) * HEAD_DIM + d;
                *(float2*)hp = make_float2(v00 * c0 - v01 * s0,
                                           v00 * s0 + v01 * c0);
                *(float2*)(hp + 8 * HEAD_DIM) =
                    make_float2(v10 * c1 - v11 * s1, v10 * s1 + v11 * c1);
            }
        }
    }
}

// ------------------- flash attention on tensor cores -----------------------
// 128q x 128k tiles, 8 warps x 16 query rows, split-bf16 (3 MMAs).
#define LDQK 72   // bf16 row stride for Q/K tiles (64 cols + 8 pad)
#define LDV 136   // bf16 row stride for V tile (128 cols + 8 pad)
// byte offsets in dynamic smem
#define OFF_QHI 0
#define OFF_QLO (128 * LDQK * 2)
#define OFF_KHI (2 * 128 * LDQK * 2)
#define OFF_KLO (3 * 128 * LDQK * 2)
#define OFF_VHI (4 * 128 * LDQK * 2)
#define OFF_VLO (4 * 128 * LDQK * 2 + 64 * LDV * 2)
#define ATTN_SMEM (4 * 128 * LDQK * 2 + 2 * 64 * LDV * 2)

__global__ void __launch_bounds__(256, 1) attn_k()
{
    extern __shared__ __align__(16) char smraw[];
    uint32_t sb = smem_u32(smraw);
    uint32_t aQhi = sb + OFF_QHI, aQlo = sb + OFF_QLO;
    uint32_t aKhi = sb + OFF_KHI, aKlo = sb + OFF_KLO;
    uint32_t aVhi = sb + OFF_VHI, aVlo = sb + OFF_VLO;

    int qb = gridDim.x - 1 - blockIdx.x;  // longest blocks first
    int h = blockIdx.y;
    int tid = threadIdx.x, wid = tid >> 5, lane = tid & 31;
    int m0 = wid * 16;                    // warp's query rows
    int rq = lane >> 2, cq = (lane & 3) * 2;

    const float* qg = g_q + ((size_t)h * S_LEN + qb * 128) * HEAD_DIM;
    const float* vg = g_v + (size_t)h * HEAD_DIM * S_LEN;

    // ---- load Q tile (contiguous 128x64 f32), scale by 1/8, split to bf16
#pragma unroll
    for (int it = 0; it < 8; it++) {
        int idx4 = tid + it * 256;
        float4 f = ((const float4*)qg)[idx4];
        f.x *= 0.125f; f.y *= 0.125f; f.z *= 0.125f; f.w *= 0.125f;
        int row = idx4 >> 4, col = (idx4 & 15) << 2;
        uint32_t h0, h1, l0, l1;
        split2(f.x, f.y, h0, l0);
        split2(f.z, f.w, h1, l1);
        uint32_t off = (uint32_t)(row * LDQK + col) * 2u;
        asm volatile("st.shared.v2.b32 [%0], {%1,%2};"
                     :: "r"(aQhi + off), "r"(h0), "r"(h1) : "memory");
        asm volatile("st.shared.v2.b32 [%0], {%1,%2};"
                     :: "r"(aQlo + off), "r"(l0), "r"(l1) : "memory");
    }

    float m[2] = {-1e30f, -1e30f};
    float l[2] = {0.f, 0.f};
    float o[8][4];
#pragma unroll
    for (int dt = 0; dt < 8; dt++)
#pragma unroll
        for (int e = 0; e < 4; e++) o[dt][e] = 0.f;

    for (int kb = 0; kb <= qb; kb++) {
        __syncthreads();  // prev iter's MMA reads done
        // ---- load K tile (contiguous 128x64 f32)
        const float* kg = g_k + ((size_t)h * S_LEN + kb * 128) * HEAD_DIM;
#pragma unroll
        for (int it = 0; it < 8; it++) {
            int idx4 = tid + it * 256;
            float4 f = ((const float4*)kg)[idx4];
            int row = idx4 >> 4, col = (idx4 & 15) << 2;
            uint32_t h0, h1, l0, l1;
            split2(f.x, f.y, h0, l0);
            split2(f.z, f.w, h1, l1);
            uint32_t off = (uint32_t)(row * LDQK + col) * 2u;
            asm volatile("st.shared.v2.b32 [%0], {%1,%2};"
                         :: "r"(aKhi + off), "r"(h0), "r"(h1) : "memory");
            asm volatile("st.shared.v2.b32 [%0], {%1,%2};"
                         :: "r"(aKlo + off), "r"(l0), "r"(l1) : "memory");
        }
        // ---- load V tile ([64 d][128 s], rows stride S_LEN)
#pragma unroll
        for (int it = 0; it < 8; it++) {
            int idx4 = tid + it * 256;
            int row = idx4 >> 5, col = (idx4 & 31) << 2;
            float4 f = *(const float4*)(vg + (size_t)row * S_LEN +
                                        kb * 128 + col);
            uint32_t h0, h1, l0, l1;
            split2(f.x, f.y, h0, l0);
            split2(f.z, f.w, h1, l1);
            uint32_t off = (uint32_t)(row * LDV + col) * 2u;
            asm volatile("st.shared.v2.b32 [%0], {%1,%2};"
                         :: "r"(aVhi + off), "r"(h0), "r"(h1) : "memory");
            asm volatile("st.shared.v2.b32 [%0], {%1,%2};"
                         :: "r"(aVlo + off), "r"(l0), "r"(l1) : "memory");
        }
        __syncthreads();

        // ---- scores: 16 n-tiles x 4 k-steps, split-bf16
        float sc[16][4];
#pragma unroll
        for (int nt = 0; nt < 16; nt++)
#pragma unroll
            for (int e = 0; e < 4; e++) sc[nt][e] = 0.f;

#pragma unroll
        for (int ks = 0; ks < 4; ks++) {
            int k0 = ks * 16;
            uint32_t ah[4], al[4];
            ldsm_x4(ah, addrA(aQhi, m0, k0, lane, LDQK));
            ldsm_x4(al, addrA(aQlo, m0, k0, lane, LDQK));
#pragma unroll
            for (int nt = 0; nt < 16; nt++) {
                uint32_t bh[2], bl[2];
                ldsm_x2(bh, addrB(aKhi, nt * 8, k0, lane, LDQK));
                ldsm_x2(bl, addrB(aKlo, nt * 8, k0, lane, LDQK));
                mma_bf16(sc[nt], ah, bh);
                mma_bf16(sc[nt], ah, bl);
                mma_bf16(sc[nt], al, bh);
            }
        }

        // ---- causal mask on diagonal tile
        if (kb == qb) {
#pragma unroll
            for (int nt = 0; nt < 16; nt++) {
#pragma unroll
                for (int e = 0; e < 4; e++) {
                    int qi = m0 + rq + ((e >> 1) << 3);
                    int kj = nt * 8 + cq + (e & 1);
                    if (kj > qi) sc[nt][e] = -1e30f;
                }
            }
        }

        // ---- online softmax (rows rq, rq+8; row spread over 4 lanes)
#pragma unroll
        for (int r = 0; r < 2; r++) {
            float mx = -1e30f;
#pragma unroll
            for (int nt = 0; nt < 16; nt++)
                mx = fmaxf(mx, fmaxf(sc[nt][2 * r], sc[nt][2 * r + 1]));
            mx = fmaxf(mx, __shfl_xor_sync(0xffffffffu, mx, 1));
            mx = fmaxf(mx, __shfl_xor_sync(0xffffffffu, mx, 2));
            float mn = fmaxf(m[r], mx);
            float corr = __expf(m[r] - mn);
            m[r] = mn;
            float rs = 0.f;
#pragma unroll
            for (int nt = 0; nt < 16; nt++) {
                float p0 = __expf(sc[nt][2 * r] - mn);
                float p1 = __expf(sc[nt][2 * r + 1] - mn);
                sc[nt][2 * r] = p0;
                sc[nt][2 * r + 1] = p1;
                rs += p0 + p1;
            }
            l[r] = l[r] * corr + rs;  // lane-partial; reduced at the end
#pragma unroll
            for (int dt = 0; dt < 8; dt++) {
                o[dt][2 * r] *= corr;
                o[dt][2 * r + 1] *= corr;
            }
        }

        // ---- PV: P C-frags repack directly into A-frags (no smem)
#pragma unroll
        for (int kp = 0; kp < 8; kp++) {
            uint32_t ph[4], pl[4];
            split2(sc[2 * kp][0], sc[2 * kp][1], ph[0], pl[0]);
            split2(sc[2 * kp][2], sc[2 * kp][3], ph[1], pl[1]);
            split2(sc[2 * kp + 1][0], sc[2 * kp + 1][1], ph[2], pl[2]);
            split2(sc[2 * kp + 1][2], sc[2 * kp + 1][3], ph[3], pl[3]);
            int k0 = kp * 16;
#pragma unroll
            for (int dt = 0; dt < 8; dt++) {
                uint32_t bh[2], bl[2];
                ldsm_x2(bh, addrB(aVhi, dt * 8, k0, lane, LDV));
                ldsm_x2(bl, addrB(aVlo, dt * 8, k0, lane, LDV));
                mma_bf16(o[dt], ph, bh);
                mma_bf16(o[dt], ph, bl);
                mma_bf16(o[dt], pl, bh);
            }
        }
    }

    // ---- finalize: reduce lane-partial l over the 4-lane row group
#pragma unroll
    for (int r = 0; r < 2; r++) {
        l[r] += __shfl_xor_sync(0xffffffffu, l[r], 1);
        l[r] += __shfl_xor_sync(0xffffffffu, l[r], 2);
    }
    float inv0 = 1.f / l[0], inv1 = 1.f / l[1];
    int r0 = qb * 128 + m0 + rq;
    float* op = g_at + (size_t)r0 * D_MODEL + h * HEAD_DIM + cq;
#pragma unroll
    for (int dt = 0; dt < 8; dt++) {
        *(float2*)(op + dt * 8) =
            make_float2(o[dt][0] * inv0, o[dt][1] * inv0);
        *(float2*)(op + 8 * D_MODEL + dt * 8) =
            make_float2(o[dt][2] * inv1, o[dt][3] * inv1);
    }
}

extern "C" void kernel_launch(void* const* d_in, const int* in_sizes, int n_in,
                              void* d_out, int out_size)
{
    const float* x    = (const float*)d_in[0];
    const float* fcos = (const float*)d_in[2];
    const float* fsin = (const float*)d_in[3];
    const float* wq  = (const float*)d_in[5];
    const float* wqb = (const float*)d_in[6];
    const float* wk  = (const float*)d_in[7];
    const float* wkb = (const float*)d_in[8];
    const float* wv  = (const float*)d_in[9];
    const float* wvb = (const float*)d_in[10];
    const float* wo  = (const float*)d_in[11];
    const float* wob = (const float*)d_in[12];
    float* out = (float*)d_out;

    static bool attr_set = false;
    if (!attr_set) {
        cudaFuncSetAttribute(attn_k,
                             cudaFuncAttributeMaxDynamicSharedMemorySize,
                             ATTN_SMEM);
        attr_set = true;
    }

    dim3 gg(D_MODEL / 128, S_LEN / 128);
    gemm_tc<MODE_Q><<<gg, 256>>>(x, wq, wqb, fcos, fsin, nullptr);
    gemm_tc<MODE_K><<<gg, 256>>>(x, wk, wkb, fcos, fsin, nullptr);
    gemm_tc<MODE_V><<<gg, 256>>>(x, wv, wvb, fcos, fsin, nullptr);
    attn_k<<<dim3(S_LEN / 128, N_HEADS), 256, ATTN_SMEM>>>();
    gemm_tc<MODE_O><<<gg, 256>>>(nullptr, wo, wob, fcos, fsin, out);
}

// round 6
// speedup vs baseline: 3.0840x; 1.0826x over previous
#include <cuda_runtime.h>
#include <cuda_bf16.h>
#include <cstdint>

#define S_LEN 4096
#define D_MODEL 1024
#define N_HEADS 16
#define HEAD_DIM 64
#define HALF_DIM 32

// ---------------- split-bf16 scratch (device globals) ----------------------
__device__ __align__(16) __nv_bfloat16 g_xhi[S_LEN * D_MODEL];
__device__ __align__(16) __nv_bfloat16 g_xlo[S_LEN * D_MODEL];
__device__ __align__(16) __nv_bfloat16 g_whi[4][D_MODEL * D_MODEL];
__device__ __align__(16) __nv_bfloat16 g_wlo[4][D_MODEL * D_MODEL];
__device__ __align__(16) __nv_bfloat16 g_qhi[N_HEADS * S_LEN * HEAD_DIM]; // [h][s][d] RoPE'd, /8
__device__ __align__(16) __nv_bfloat16 g_qlo[N_HEADS * S_LEN * HEAD_DIM];
__device__ __align__(16) __nv_bfloat16 g_khi[N_HEADS * S_LEN * HEAD_DIM]; // [h][s][d] RoPE'd
__device__ __align__(16) __nv_bfloat16 g_klo[N_HEADS * S_LEN * HEAD_DIM];
__device__ __align__(16) __nv_bfloat16 g_vhi[N_HEADS * HEAD_DIM * S_LEN]; // [h][d][s]
__device__ __align__(16) __nv_bfloat16 g_vlo[N_HEADS * HEAD_DIM * S_LEN];
__device__ __align__(16) __nv_bfloat16 g_ahi[S_LEN * D_MODEL];            // attn out [s][h*64+d]
__device__ __align__(16) __nv_bfloat16 g_alo[S_LEN * D_MODEL];

enum { MODE_Q = 0, MODE_K = 1, MODE_V = 2, MODE_O = 3 };

// ---------------- mma.sync helpers (PTX baseline, legal on sm_103) ---------
__device__ __forceinline__ uint32_t smem_u32(const void* p) {
    uint32_t a;
    asm("{ .reg .u64 t; cvta.to.shared.u64 t, %1; cvt.u32.u64 %0, t; }"
        : "=r"(a) : "l"(p));
    return a;
}

__device__ __forceinline__ void ldsm_x4(uint32_t* r, uint32_t addr) {
    asm volatile("ldmatrix.sync.aligned.m8n8.x4.shared.b16 {%0,%1,%2,%3}, [%4];"
                 : "=r"(r[0]), "=r"(r[1]), "=r"(r[2]), "=r"(r[3]) : "r"(addr));
}
__device__ __forceinline__ void ldsm_x2(uint32_t* r, uint32_t addr) {
    asm volatile("ldmatrix.sync.aligned.m8n8.x2.shared.b16 {%0,%1}, [%2];"
                 : "=r"(r[0]), "=r"(r[1]) : "r"(addr));
}

__device__ __forceinline__ void mma_bf16(float* c, const uint32_t* a,
                                         const uint32_t* b) {
    asm volatile(
        "mma.sync.aligned.m16n8k16.row.col.f32.bf16.bf16.f32 "
        "{%0,%1,%2,%3}, {%4,%5,%6,%7}, {%8,%9}, {%0,%1,%2,%3};"
        : "+f"(c[0]), "+f"(c[1]), "+f"(c[2]), "+f"(c[3])
        : "r"(a[0]), "r"(a[1]), "r"(a[2]), "r"(a[3]), "r"(b[0]), "r"(b[1]));
}

__device__ __forceinline__ uint32_t pk_bf2(__nv_bfloat16 a, __nv_bfloat16 b) {
    __nv_bfloat162 t = __halves2bfloat162(a, b);
    return *reinterpret_cast<uint32_t*>(&t);
}

__device__ __forceinline__ void split2(float a, float b,
                                       uint32_t& hi, uint32_t& lo) {
    __nv_bfloat16 ha = __float2bfloat16_rn(a);
    __nv_bfloat16 hb = __float2bfloat16_rn(b);
    __nv_bfloat16 la = __float2bfloat16_rn(a - __bfloat162float(ha));
    __nv_bfloat16 lb = __float2bfloat16_rn(b - __bfloat162float(hb));
    hi = pk_bf2(ha, hb);
    lo = pk_bf2(la, lb);
}

__device__ __forceinline__ uint32_t addrA(uint32_t base, int m0, int k0,
                                          int lane, int ld) {
    int r = m0 + (lane & 15);
    int c = k0 + ((lane >> 4) << 3);
    return base + (uint32_t)(r * ld + c) * 2u;
}
__device__ __forceinline__ uint32_t addrB(uint32_t base, int n0, int k0,
                                          int lane, int ld) {
    int r = n0 + (lane & 7);
    int c = k0 + (((lane >> 3) & 1) << 3);
    return base + (uint32_t)(r * ld + c) * 2u;
}

// ---------------- pre-pass: f32 -> split-bf16 ------------------------------
// TAG: 0=x, 1..4 = wq,wk,wv,wo
template <int TAG>
__global__ void __launch_bounds__(256) conv_k(const float* __restrict__ in, int n4)
{
    __nv_bfloat16* hi;
    __nv_bfloat16* lo;
    if (TAG == 0) { hi = g_xhi; lo = g_xlo; }
    else { hi = g_whi[TAG - 1]; lo = g_wlo[TAG - 1]; }

    int idx = blockIdx.x * 256 + threadIdx.x;
    if (idx >= n4) return;
    float4 f = ((const float4*)in)[idx];
    uint32_t h0, h1, l0, l1;
    split2(f.x, f.y, h0, l0);
    split2(f.z, f.w, h1, l1);
    ((uint2*)hi)[idx] = make_uint2(h0, h1);
    ((uint2*)lo)[idx] = make_uint2(l0, l1);
}

#define LDT 40  // GEMM smem row stride (bf16)

// ------------------- tensor-core GEMM: C = X @ W^T + bias ------------------
// 128x128 CTA tile, 8 warps (2M x 4N), warp tile 64x32, BK=32, split-bf16.
// Inputs pre-split to bf16 hi/lo; inner loop is pure ld/sts/ldsm/mma.
template <int MODE>
__global__ void __launch_bounds__(256, 1) gemm_tc(
    const float* __restrict__ bias, const float* __restrict__ fcos,
    const float* __restrict__ fsin, float* __restrict__ oout)
{
    __shared__ __nv_bfloat16 sAhi[128 * LDT], sAlo[128 * LDT];
    __shared__ __nv_bfloat16 sBhi[128 * LDT], sBlo[128 * LDT];

    const __nv_bfloat16* Ahi = (MODE == MODE_O) ? g_ahi : g_xhi;
    const __nv_bfloat16* Alo = (MODE == MODE_O) ? g_alo : g_xlo;
    const __nv_bfloat16* Bhi = g_whi[MODE];
    const __nv_bfloat16* Blo = g_wlo[MODE];

    uint32_t aAhi = smem_u32(sAhi), aAlo = smem_u32(sAlo);
    uint32_t aBhi = smem_u32(sBhi), aBlo = smem_u32(sBlo);

    int tid = threadIdx.x, wid = tid >> 5, lane = tid & 31;
    int wm = wid >> 2, wn = wid & 3;
    int m0 = wm * 64, n0 = wn * 32;
    int bm = blockIdx.y * 128, bn = blockIdx.x * 128;

    int lrow = tid >> 1, lks = (tid & 1) * 16;
    const uint4* pAh = (const uint4*)(Ahi + (size_t)(bm + lrow) * D_MODEL + lks);
    const uint4* pAl = (const uint4*)(Alo + (size_t)(bm + lrow) * D_MODEL + lks);
    const uint4* pBh = (const uint4*)(Bhi + (size_t)(bn + lrow) * D_MODEL + lks);
    const uint4* pBl = (const uint4*)(Blo + (size_t)(bn + lrow) * D_MODEL + lks);

    uint4 vah[2], val[2], vbh[2], vbl[2];
#pragma unroll
    for (int v = 0; v < 2; v++) {
        vah[v] = pAh[v]; val[v] = pAl[v];
        vbh[v] = pBh[v]; vbl[v] = pBl[v];
    }

    float acc[4][4][4];
#pragma unroll
    for (int i = 0; i < 4; i++)
#pragma unroll
        for (int j = 0; j < 4; j++)
#pragma unroll
            for (int e = 0; e < 4; e++) acc[i][j][e] = 0.f;

    uint32_t soff = (uint32_t)(lrow * LDT + lks) * 2u;

    for (int c = 0; c < 32; c++) {
#pragma unroll
        for (int v = 0; v < 2; v++) {
            asm volatile("st.shared.v4.b32 [%0], {%1,%2,%3,%4};"
                :: "r"(aAhi + soff + v * 16u), "r"(vah[v].x), "r"(vah[v].y),
                   "r"(vah[v].z), "r"(vah[v].w) : "memory");
            asm volatile("st.shared.v4.b32 [%0], {%1,%2,%3,%4};"
                :: "r"(aAlo + soff + v * 16u), "r"(val[v].x), "r"(val[v].y),
                   "r"(val[v].z), "r"(val[v].w) : "memory");
            asm volatile("st.shared.v4.b32 [%0], {%1,%2,%3,%4};"
                :: "r"(aBhi + soff + v * 16u), "r"(vbh[v].x), "r"(vbh[v].y),
                   "r"(vbh[v].z), "r"(vbh[v].w) : "memory");
            asm volatile("st.shared.v4.b32 [%0], {%1,%2,%3,%4};"
                :: "r"(aBlo + soff + v * 16u), "r"(vbl[v].x), "r"(vbl[v].y),
                   "r"(vbl[v].z), "r"(vbl[v].w) : "memory");
        }
        __syncthreads();
        if (c < 31) {
            int co = (c + 1) * 4;  // uint4 offset per chunk (32 bf16 = 4 uint4)
#pragma unroll
            for (int v = 0; v < 2; v++) {
                vah[v] = pAh[co + v]; val[v] = pAl[co + v];
                vbh[v] = pBh[co + v]; vbl[v] = pBl[co + v];
            }
        }
#pragma unroll
        for (int ks = 0; ks < 2; ks++) {
            int k0 = ks * 16;
            uint32_t bh[4][2], bl[4][2];
#pragma unroll
            for (int nt = 0; nt < 4; nt++) {
                ldsm_x2(bh[nt], addrB(aBhi, n0 + nt * 8, k0, lane, LDT));
                ldsm_x2(bl[nt], addrB(aBlo, n0 + nt * 8, k0, lane, LDT));
            }
#pragma unroll
            for (int mt = 0; mt < 4; mt++) {
                uint32_t ah[4], al[4];
                ldsm_x4(ah, addrA(aAhi, m0 + mt * 16, k0, lane, LDT));
                ldsm_x4(al, addrA(aAlo, m0 + mt * 16, k0, lane, LDT));
#pragma unroll
                for (int nt = 0; nt < 4; nt++) {
                    mma_bf16(acc[mt][nt], ah, bh[nt]);
                    mma_bf16(acc[mt][nt], ah, bl[nt]);
                    mma_bf16(acc[mt][nt], al, bh[nt]);
                }
            }
        }
        __syncthreads();
    }

    // ---------------- epilogue ----------------
    int rq = lane >> 2;          // fragment row within m16
    int cq = (lane & 3) * 2;     // fragment col pair within n8
#pragma unroll
    for (int mt = 0; mt < 4; mt++) {
#pragma unroll
        for (int nt = 0; nt < 4; nt++) {
            int r0 = bm + m0 + mt * 16 + rq;   // global rows r0, r0+8
            int cg = bn + n0 + nt * 8 + cq;    // global col (even)
            float b0 = bias[cg], b1 = bias[cg + 1];
            float v00 = acc[mt][nt][0] + b0, v01 = acc[mt][nt][1] + b1;
            float v10 = acc[mt][nt][2] + b0, v11 = acc[mt][nt][3] + b1;
            if (MODE == MODE_O) {
                *(float2*)(oout + (size_t)r0 * D_MODEL + cg) =
                    make_float2(v00, v01);
                *(float2*)(oout + (size_t)(r0 + 8) * D_MODEL + cg) =
                    make_float2(v10, v11);
            } else if (MODE == MODE_V) {
                // [h][d][s] split-bf16
                int h = cg >> 6, d = cg & 63;
                size_t o0 = ((size_t)h * HEAD_DIM + d) * S_LEN;
                uint32_t h0, l0, h1, l1;
                split2(v00, v10, h0, l0);   // same d, rows r0 & r0+8? no:
                // careful: rows r0,r0+8 are adjacent in s; cols d,d+1 separate rows.
                g_vhi[o0 + r0]              = __float2bfloat16_rn(v00);
                g_vhi[o0 + r0 + 8]          = __float2bfloat16_rn(v10);
                g_vhi[o0 + S_LEN + r0]      = __float2bfloat16_rn(v01);
                g_vhi[o0 + S_LEN + r0 + 8]  = __float2bfloat16_rn(v11);
                g_vlo[o0 + r0]              = __float2bfloat16_rn(v00 - __bfloat162float(__float2bfloat16_rn(v00)));
                g_vlo[o0 + r0 + 8]          = __float2bfloat16_rn(v10 - __bfloat162float(__float2bfloat16_rn(v10)));
                g_vlo[o0 + S_LEN + r0]      = __float2bfloat16_rn(v01 - __bfloat162float(__float2bfloat16_rn(v01)));
                g_vlo[o0 + S_LEN + r0 + 8]  = __float2bfloat16_rn(v11 - __bfloat162float(__float2bfloat16_rn(v11)));
                (void)h0; (void)l0; (void)h1; (void)l1;
            } else {
                // Q/K: RoPE, write [h][s][d] split-bf16 (pair (d,d+1) in-fragment)
                int h = cg >> 6, d = cg & 63;
                float c0 = fcos[(size_t)r0 * HALF_DIM + (d >> 1)];
                float s0 = fsin[(size_t)r0 * HALF_DIM + (d >> 1)];
                float c1 = fcos[(size_t)(r0 + 8) * HALF_DIM + (d >> 1)];
                float s1 = fsin[(size_t)(r0 + 8) * HALF_DIM + (d >> 1)];
                float q00 = v00 * c0 - v01 * s0, q01 = v00 * s0 + v01 * c0;
                float q10 = v10 * c1 - v11 * s1, q11 = v10 * s1 + v11 * c1;
                __nv_bfloat16* dh = (MODE == MODE_Q) ? g_qhi : g_khi;
                __nv_bfloat16* dl = (MODE == MODE_Q) ? g_qlo : g_klo;
                if (MODE == MODE_Q) {
                    q00 *= 0.125f; q01 *= 0.125f; q10 *= 0.125f; q11 *= 0.125f;
                }
                size_t o0 = ((size_t)h * S_LEN + r0) * HEAD_DIM + d;
                uint32_t hh, ll;
                split2(q00, q01, hh, ll);
                *(uint32_t*)(dh + o0) = hh;
                *(uint32_t*)(dl + o0) = ll;
                split2(q10, q11, hh, ll);
                *(uint32_t*)(dh + o0 + 8 * HEAD_DIM) = hh;
                *(uint32_t*)(dl + o0 + 8 * HEAD_DIM) = ll;
            }
        }
    }
}

// ------------------- flash attention on tensor cores -----------------------
// 128q x 128k tiles, 8 warps x 16 query rows, split-bf16 (3 MMAs).
#define LDQK 72   // bf16 row stride for Q/K tiles (64 cols + 8 pad)
#define LDV 136   // bf16 row stride for V tile (128 cols + 8 pad)
#define OFF_QHI 0
#define OFF_QLO (128 * LDQK * 2)
#define OFF_KHI (2 * 128 * LDQK * 2)
#define OFF_KLO (3 * 128 * LDQK * 2)
#define OFF_VHI (4 * 128 * LDQK * 2)
#define OFF_VLO (4 * 128 * LDQK * 2 + 64 * LDV * 2)
#define ATTN_SMEM (4 * 128 * LDQK * 2 + 2 * 64 * LDV * 2)

__global__ void __launch_bounds__(256, 1) attn_k()
{
    extern __shared__ __align__(16) char smraw[];
    uint32_t sb = smem_u32(smraw);
    uint32_t aQhi = sb + OFF_QHI, aQlo = sb + OFF_QLO;
    uint32_t aKhi = sb + OFF_KHI, aKlo = sb + OFF_KLO;
    uint32_t aVhi = sb + OFF_VHI, aVlo = sb + OFF_VLO;

    int qb = gridDim.x - 1 - blockIdx.x;  // longest blocks first
    int h = blockIdx.y;
    int tid = threadIdx.x, wid = tid >> 5, lane = tid & 31;
    int m0 = wid * 16;                    // warp's query rows
    int rq = lane >> 2, cq = (lane & 3) * 2;

    const __nv_bfloat16* qhg = g_qhi + ((size_t)h * S_LEN + qb * 128) * HEAD_DIM;
    const __nv_bfloat16* qlg = g_qlo + ((size_t)h * S_LEN + qb * 128) * HEAD_DIM;

    // ---- load Q tile (128x64 bf16 hi/lo, contiguous)
#pragma unroll
    for (int it = 0; it < 4; it++) {
        int idx4 = tid + it * 256;              // uint4 index; 8 bf16 each
        int row = idx4 >> 3, col = (idx4 & 7) << 3;
        uint4 vh = ((const uint4*)qhg)[idx4];
        uint4 vl = ((const uint4*)qlg)[idx4];
        uint32_t off = (uint32_t)(row * LDQK + col) * 2u;
        asm volatile("st.shared.v4.b32 [%0], {%1,%2,%3,%4};"
                     :: "r"(aQhi + off), "r"(vh.x), "r"(vh.y), "r"(vh.z), "r"(vh.w)
                     : "memory");
        asm volatile("st.shared.v4.b32 [%0], {%1,%2,%3,%4};"
                     :: "r"(aQlo + off), "r"(vl.x), "r"(vl.y), "r"(vl.z), "r"(vl.w)
                     : "memory");
    }

    float m[2] = {-1e30f, -1e30f};
    float l[2] = {0.f, 0.f};
    float o[8][4];
#pragma unroll
    for (int dt = 0; dt < 8; dt++)
#pragma unroll
        for (int e = 0; e < 4; e++) o[dt][e] = 0.f;

    for (int kb = 0; kb <= qb; kb++) {
        __syncthreads();  // prev iter's MMA reads done
        // ---- load K tile (128x64 bf16 hi/lo, contiguous)
        const __nv_bfloat16* khg = g_khi + ((size_t)h * S_LEN + kb * 128) * HEAD_DIM;
        const __nv_bfloat16* klg = g_klo + ((size_t)h * S_LEN + kb * 128) * HEAD_DIM;
#pragma unroll
        for (int it = 0; it < 4; it++) {
            int idx4 = tid + it * 256;
            int row = idx4 >> 3, col = (idx4 & 7) << 3;
            uint4 vh = ((const uint4*)khg)[idx4];
            uint4 vl = ((const uint4*)klg)[idx4];
            uint32_t off = (uint32_t)(row * LDQK + col) * 2u;
            asm volatile("st.shared.v4.b32 [%0], {%1,%2,%3,%4};"
                         :: "r"(aKhi + off), "r"(vh.x), "r"(vh.y), "r"(vh.z), "r"(vh.w)
                         : "memory");
            asm volatile("st.shared.v4.b32 [%0], {%1,%2,%3,%4};"
                         :: "r"(aKlo + off), "r"(vl.x), "r"(vl.y), "r"(vl.z), "r"(vl.w)
                         : "memory");
        }
        // ---- load V tile ([64 d][128 s] bf16 hi/lo, rows stride S_LEN)
        const __nv_bfloat16* vhg = g_vhi + (size_t)h * HEAD_DIM * S_LEN + kb * 128;
        const __nv_bfloat16* vlg = g_vlo + (size_t)h * HEAD_DIM * S_LEN + kb * 128;
#pragma unroll
        for (int it = 0; it < 4; it++) {
            int idx4 = tid + it * 256;
            int row = idx4 >> 4, col = (idx4 & 15) << 3;
            uint4 vh = *(const uint4*)(vhg + (size_t)row * S_LEN + col);
            uint4 vl = *(const uint4*)(vlg + (size_t)row * S_LEN + col);
            uint32_t off = (uint32_t)(row * LDV + col) * 2u;
            asm volatile("st.shared.v4.b32 [%0], {%1,%2,%3,%4};"
                         :: "r"(aVhi + off), "r"(vh.x), "r"(vh.y), "r"(vh.z), "r"(vh.w)
                         : "memory");
            asm volatile("st.shared.v4.b32 [%0], {%1,%2,%3,%4};"
                         :: "r"(aVlo + off), "r"(vl.x), "r"(vl.y), "r"(vl.z), "r"(vl.w)
                         : "memory");
        }
        __syncthreads();

        // ---- scores: 16 n-tiles x 4 k-steps, split-bf16
        float sc[16][4];
#pragma unroll
        for (int nt = 0; nt < 16; nt++)
#pragma unroll
            for (int e = 0; e < 4; e++) sc[nt][e] = 0.f;

#pragma unroll
        for (int ks = 0; ks < 4; ks++) {
            int k0 = ks * 16;
            uint32_t ah[4], al[4];
            ldsm_x4(ah, addrA(aQhi, m0, k0, lane, LDQK));
            ldsm_x4(al, addrA(aQlo, m0, k0, lane, LDQK));
#pragma unroll
            for (int nt = 0; nt < 16; nt++) {
                uint32_t bh[2], bl[2];
                ldsm_x2(bh, addrB(aKhi, nt * 8, k0, lane, LDQK));
                ldsm_x2(bl, addrB(aKlo, nt * 8, k0, lane, LDQK));
                mma_bf16(sc[nt], ah, bh);
                mma_bf16(sc[nt], ah, bl);
                mma_bf16(sc[nt], al, bh);
            }
        }

        // ---- causal mask on diagonal tile
        if (kb == qb) {
#pragma unroll
            for (int nt = 0; nt < 16; nt++) {
#pragma unroll
                for (int e = 0; e < 4; e++) {
                    int qi = m0 + rq + ((e >> 1) << 3);
                    int kj = nt * 8 + cq + (e & 1);
                    if (kj > qi) sc[nt][e] = -1e30f;
                }
            }
        }

        // ---- online softmax (rows rq, rq+8; row spread over 4 lanes)
#pragma unroll
        for (int r = 0; r < 2; r++) {
            float mx = -1e30f;
#pragma unroll
            for (int nt = 0; nt < 16; nt++)
                mx = fmaxf(mx, fmaxf(sc[nt][2 * r], sc[nt][2 * r + 1]));
            mx = fmaxf(mx, __shfl_xor_sync(0xffffffffu, mx, 1));
            mx = fmaxf(mx, __shfl_xor_sync(0xffffffffu, mx, 2));
            float mn = fmaxf(m[r], mx);
            float corr = __expf(m[r] - mn);
            m[r] = mn;
            float rs = 0.f;
#pragma unroll
            for (int nt = 0; nt < 16; nt++) {
                float p0 = __expf(sc[nt][2 * r] - mn);
                float p1 = __expf(sc[nt][2 * r + 1] - mn);
                sc[nt][2 * r] = p0;
                sc[nt][2 * r + 1] = p1;
                rs += p0 + p1;
            }
            l[r] = l[r] * corr + rs;  // lane-partial; reduced at the end
#pragma unroll
            for (int dt = 0; dt < 8; dt++) {
                o[dt][2 * r] *= corr;
                o[dt][2 * r + 1] *= corr;
            }
        }

        // ---- PV: P C-frags repack directly into A-frags (no smem)
#pragma unroll
        for (int kp = 0; kp < 8; kp++) {
            uint32_t ph[4], pl[4];
            split2(sc[2 * kp][0], sc[2 * kp][1], ph[0], pl[0]);
            split2(sc[2 * kp][2], sc[2 * kp][3], ph[1], pl[1]);
            split2(sc[2 * kp + 1][0], sc[2 * kp + 1][1], ph[2], pl[2]);
            split2(sc[2 * kp + 1][2], sc[2 * kp + 1][3], ph[3], pl[3]);
            int k0 = kp * 16;
#pragma unroll
            for (int dt = 0; dt < 8; dt++) {
                uint32_t bh[2], bl[2];
                ldsm_x2(bh, addrB(aVhi, dt * 8, k0, lane, LDV));
                ldsm_x2(bl, addrB(aVlo, dt * 8, k0, lane, LDV));
                mma_bf16(o[dt], ph, bh);
                mma_bf16(o[dt], ph, bl);
                mma_bf16(o[dt], pl, bh);
            }
        }
    }

    // ---- finalize: reduce lane-partial l, store split-bf16 for O-GEMM
#pragma unroll
    for (int r = 0; r < 2; r++) {
        l[r] += __shfl_xor_sync(0xffffffffu, l[r], 1);
        l[r] += __shfl_xor_sync(0xffffffffu, l[r], 2);
    }
    float inv0 = 1.f / l[0], inv1 = 1.f / l[1];
    int r0 = qb * 128 + m0 + rq;
    size_t ob = (size_t)r0 * D_MODEL + h * HEAD_DIM + cq;
#pragma unroll
    for (int dt = 0; dt < 8; dt++) {
        uint32_t hh, ll;
        split2(o[dt][0] * inv0, o[dt][1] * inv0, hh, ll);
        *(uint32_t*)(g_ahi + ob + dt * 8) = hh;
        *(uint32_t*)(g_alo + ob + dt * 8) = ll;
        split2(o[dt][2] * inv1, o[dt][3] * inv1, hh, ll);
        *(uint32_t*)(g_ahi + ob + 8 * D_MODEL + dt * 8) = hh;
        *(uint32_t*)(g_alo + ob + 8 * D_MODEL + dt * 8) = ll;
    }
}

extern "C" void kernel_launch(void* const* d_in, const int* in_sizes, int n_in,
                              void* d_out, int out_size)
{
    const float* x    = (const float*)d_in[0];
    const float* fcos = (const float*)d_in[2];
    const float* fsin = (const float*)d_in[3];
    const float* wq  = (const float*)d_in[5];
    const float* wqb = (const float*)d_in[6];
    const float* wk  = (const float*)d_in[7];
    const float* wkb = (const float*)d_in[8];
    const float* wv  = (const float*)d_in[9];
    const float* wvb = (const float*)d_in[10];
    const float* wo  = (const float*)d_in[11];
    const float* wob = (const float*)d_in[12];
    float* out = (float*)d_out;

    static bool attr_set = false;
    if (!attr_set) {
        cudaFuncSetAttribute(attn_k,
                             cudaFuncAttributeMaxDynamicSharedMemorySize,
                             ATTN_SMEM);
        attr_set = true;
    }

    int n4x = S_LEN * D_MODEL / 4;
    int n4w = D_MODEL * D_MODEL / 4;
    conv_k<0><<<n4x / 256, 256>>>(x, n4x);
    conv_k<1><<<n4w / 256, 256>>>(wq, n4w);
    conv_k<2><<<n4w / 256, 256>>>(wk, n4w);
    conv_k<3><<<n4w / 256, 256>>>(wv, n4w);
    conv_k<4><<<n4w / 256, 256>>>(wo, n4w);

    dim3 gg(D_MODEL / 128, S_LEN / 128);
    gemm_tc<MODE_Q><<<gg, 256>>>(wqb, fcos, fsin, nullptr);
    gemm_tc<MODE_K><<<gg, 256>>>(wkb, fcos, fsin, nullptr);
    gemm_tc<MODE_V><<<gg, 256>>>(wvb, fcos, fsin, nullptr);
    attn_k<<<dim3(S_LEN / 128, N_HEADS), 256, ATTN_SMEM>>>();
    gemm_tc<MODE_O><<<gg, 256>>>(wob, fcos, fsin, out);
}